// round 11
// baseline (speedup 1.0000x reference)
#include <cuda_runtime.h>
#include <cuda_bf16.h>
#include <cuda_fp16.h>
#include <mma.h>

using namespace nvcuda;

#define BB    64
#define TXX   1024
#define AD    1024
#define UN    1024
#define VOC   32000
#define ED    512
#define KXIN  2560
#define NZ    4096
#define ZSPLITS 8      // 4 (bf16 ctx part) + 4 (fp16 emb+h part)
#define TCH   16

#define TP 72          // smem tile pitch (elems): 64 + 8

// ---------------- scratch (__device__ globals; NEVER passed from host) ----------------
__device__ __align__(16) float g_pctx[TCH * BB * AD];
__device__ __align__(16) __nv_bfloat16 g_xz_hi[BB * AD];     // ctx rows only (K 0..1023)
__device__ __align__(16) __nv_bfloat16 g_xz_lo[BB * AD];
__device__ __align__(16) half g_xe_h16[BB * (ED + UN)];      // emb+h rows (K 1024..2559)
__device__ __align__(16) half g_xv_h16[BB * UN];
__device__ __align__(16) float g_zpart[ZSPLITS * BB * NZ];
__device__ __align__(16) float g_logits[BB * VOC];
__device__ float g_smax[BB * 8];
__device__ float g_ssum[BB * 8];

__device__ __forceinline__ float sigf(float x) { return 1.0f / (1.0f + __expf(-x)); }
__device__ __forceinline__ float tanhfast(float x) {
    float e = __expf(2.0f * x);
    return 1.0f - 2.0f / (e + 1.0f);
}

__device__ __forceinline__ void split_write(__nv_bfloat16* hi, __nv_bfloat16* lo,
                                            size_t idx, float v) {
    __nv_bfloat16 h = __float2bfloat16(v);
    hi[idx] = h;
    lo[idx] = __float2bfloat16(v - __bfloat162float(h));
}

// ---------------- K1: context partial sums ----------------
__global__ void ctx_partial(const float* __restrict__ a) {
    int d4 = threadIdx.x;
    int b  = blockIdx.y;
    int t0 = blockIdx.x * 64;
    const float4* p = (const float4*)(a + ((size_t)b * TXX + t0) * AD) + d4;
    float4 s = make_float4(0.f, 0.f, 0.f, 0.f);
#pragma unroll 8
    for (int t = 0; t < 64; t++) {
        float4 v = p[(size_t)t * 256];
        s.x += v.x; s.y += v.y; s.z += v.z; s.w += v.w;
    }
    ((float4*)g_pctx)[((size_t)blockIdx.x * BB + b) * 256 + d4] = s;
}

// ---------------- K2: finalize ctx + build operand images ----------------
__global__ void ctx_finalize(const int* __restrict__ X, const float* __restrict__ emb,
                             const float* __restrict__ h,
                             float* __restrict__ o_ctx, float* __restrict__ o_alpha) {
    int b = blockIdx.y;
    int d = blockIdx.x * 256 + threadIdx.x;
    float s = 0.f;
#pragma unroll
    for (int j = 0; j < TCH; j++) s += g_pctx[((size_t)j * BB + b) * AD + d];
    o_ctx[b * AD + d]    = s;
    o_alpha[b * TXX + d] = 1.0f;
    split_write(g_xz_hi, g_xz_lo, (size_t)b * AD + d, s);          // ctx: bf16 hi/lo
    if (d < ED) {
        int tok = X[b];
        g_xe_h16[(size_t)b * (ED + UN) + d] = __float2half_rn(emb[(size_t)tok * ED + d]);
    }
    g_xe_h16[(size_t)b * (ED + UN) + ED + d] = __float2half_rn(h[b * UN + d]);
}

// ---------------- wgemm: bf16 hi/lo 3-term (context K segment) ----------------
__global__ void __launch_bounds__(128, 4)
wgemm(const float* __restrict__ Wa, int ldw, int ldx, int nchunks, int ldo) {
    __shared__ __align__(32) __nv_bfloat16 sm[4 * 64 * TP];
    __nv_bfloat16* Ah = sm;
    __nv_bfloat16* Al = sm + 4608;
    __nv_bfloat16* Bh = sm + 9216;
    __nv_bfloat16* Bl = sm + 13824;

    int tid = threadIdx.x, w = tid >> 5;
    int n0 = blockIdx.x * 64;
    int k0 = blockIdx.y * nchunks * 64;
    float* out = g_zpart + (size_t)blockIdx.y * BB * NZ;

    wmma::fragment<wmma::accumulator, 16, 16, 16, float> acc[4];
#pragma unroll
    for (int i = 0; i < 4; i++) wmma::fill_fragment(acc[i], 0.0f);

    float4 pf[8];
    auto ldB = [&](int kg0) {
#pragma unroll
        for (int i = 0; i < 8; i++) {
            int idx = tid + i * 128;
            int k = idx >> 4, f4c = idx & 15;
            pf[i] = __ldg((const float4*)(Wa + (size_t)(kg0 + k) * ldw + n0) + f4c);
        }
    };

    ldB(k0);
    for (int ci = 0; ci < nchunks; ci++) {
        int kg0 = k0 + ci * 64;
        __syncthreads();
#pragma unroll
        for (int i = 0; i < 4; i++) {
            int idx = tid + i * 128;
            int row = idx >> 3, j = idx & 7;
            size_t so = ((size_t)row * ldx + kg0) / 8 + j;
            ((uint4*)Ah)[row * 9 + j] = ((const uint4*)g_xz_hi)[so];
            ((uint4*)Al)[row * 9 + j] = ((const uint4*)g_xz_lo)[so];
        }
#pragma unroll
        for (int i = 0; i < 8; i++) {
            int idx = tid + i * 128;
            int k = idx >> 4, f4c = idx & 15;
            float4 v = pf[i];
            __nv_bfloat16 h0 = __float2bfloat16(v.x), h1 = __float2bfloat16(v.y);
            __nv_bfloat16 h2 = __float2bfloat16(v.z), h3 = __float2bfloat16(v.w);
            __nv_bfloat16 l0 = __float2bfloat16(v.x - __bfloat162float(h0));
            __nv_bfloat16 l1 = __float2bfloat16(v.y - __bfloat162float(h1));
            __nv_bfloat16 l2 = __float2bfloat16(v.z - __bfloat162float(h2));
            __nv_bfloat16 l3 = __float2bfloat16(v.w - __bfloat162float(h3));
            int bo = k * TP + f4c * 4;
            *(__nv_bfloat162*)(Bh + bo)     = __halves2bfloat162(h0, h1);
            *(__nv_bfloat162*)(Bh + bo + 2) = __halves2bfloat162(h2, h3);
            *(__nv_bfloat162*)(Bl + bo)     = __halves2bfloat162(l0, l1);
            *(__nv_bfloat162*)(Bl + bo + 2) = __halves2bfloat162(l2, l3);
        }
        __syncthreads();
        if (ci + 1 < nchunks) ldB(kg0 + 64);
#pragma unroll
        for (int kt = 0; kt < 4; kt++) {
            wmma::fragment<wmma::matrix_b, 16, 16, 16, __nv_bfloat16, wmma::row_major> bh, bl;
            wmma::load_matrix_sync(bh, Bh + kt * 16 * TP + w * 16, TP);
            wmma::load_matrix_sync(bl, Bl + kt * 16 * TP + w * 16, TP);
            wmma::fragment<wmma::matrix_a, 16, 16, 16, __nv_bfloat16, wmma::row_major> af[4];
#pragma unroll
            for (int mt = 0; mt < 4; mt++)
                wmma::load_matrix_sync(af[mt], Ah + mt * 16 * TP + kt * 16, TP);
#pragma unroll
            for (int mt = 0; mt < 4; mt++) wmma::mma_sync(acc[mt], af[mt], bh, acc[mt]);
#pragma unroll
            for (int mt = 0; mt < 4; mt++) wmma::mma_sync(acc[mt], af[mt], bl, acc[mt]);
#pragma unroll
            for (int mt = 0; mt < 4; mt++)
                wmma::load_matrix_sync(af[mt], Al + mt * 16 * TP + kt * 16, TP);
#pragma unroll
            for (int mt = 0; mt < 4; mt++) wmma::mma_sync(acc[mt], af[mt], bh, acc[mt]);
        }
    }
#pragma unroll
    for (int mt = 0; mt < 4; mt++)
        wmma::store_matrix_sync(out + (size_t)(mt * 16) * ldo + n0 + w * 16,
                                acc[mt], ldo, wmma::mem_row_major);
}

// ---------------- hgemm16: fp16 single-pass GEMM (vgemm + zgemm emb/h segment) ----------------
__global__ void __launch_bounds__(128, 4)
hgemm16(const float* __restrict__ Wa, const float* __restrict__ Wb, int kbound, int ldw,
        int in_sel, int ldx, int nchunks, int out_sel, int zoff, int ldo) {
    __shared__ __align__(32) half sm[2 * 64 * TP];
    half* Ah = sm;
    half* Bh = sm + 4608;

    const half* X = in_sel ? g_xv_h16 : g_xe_h16;

    int tid = threadIdx.x, w = tid >> 5;
    int n0 = blockIdx.x * 64;
    int k0 = blockIdx.y * nchunks * 64;
    float* out = out_sel ? g_logits
                         : (g_zpart + (size_t)(zoff + blockIdx.y) * BB * NZ);

    wmma::fragment<wmma::accumulator, 16, 16, 16, float> acc[4];
#pragma unroll
    for (int i = 0; i < 4; i++) wmma::fill_fragment(acc[i], 0.0f);

    uint4  pa[4];
    float4 pb[8];
    auto ldAB = [&](int kg0) {
#pragma unroll
        for (int i = 0; i < 4; i++) {
            int idx = tid + i * 128;
            int row = idx >> 3, j = idx & 7;
            pa[i] = ((const uint4*)X)[(size_t)row * (ldx / 8) + kg0 / 8 + j];
        }
#pragma unroll
        for (int i = 0; i < 8; i++) {
            int idx = tid + i * 128;
            int k = idx >> 4, f4c = idx & 15;
            int kg = kg0 + k;
            const float* wrow = (kg < kbound) ? (Wa + (size_t)kg * ldw)
                                              : (Wb + (size_t)(kg - kbound) * ldw);
            pb[i] = __ldg((const float4*)(wrow + n0) + f4c);
        }
    };

    ldAB(k0);
    for (int ci = 0; ci < nchunks; ci++) {
        __syncthreads();
#pragma unroll
        for (int i = 0; i < 4; i++) {
            int idx = tid + i * 128;
            int row = idx >> 3, j = idx & 7;
            ((uint4*)Ah)[row * 9 + j] = pa[i];
        }
#pragma unroll
        for (int i = 0; i < 8; i++) {
            int idx = tid + i * 128;
            int k = idx >> 4, f4c = idx & 15;
            float4 v = pb[i];
            half2 h01 = __floats2half2_rn(v.x, v.y);
            half2 h23 = __floats2half2_rn(v.z, v.w);
            int bo = k * TP + f4c * 4;
            *(half2*)(Bh + bo)     = h01;
            *(half2*)(Bh + bo + 2) = h23;
        }
        __syncthreads();
        if (ci + 1 < nchunks) ldAB(k0 + (ci + 1) * 64);
#pragma unroll
        for (int kt = 0; kt < 4; kt++) {
            wmma::fragment<wmma::matrix_b, 16, 16, 16, half, wmma::row_major> bf;
            wmma::load_matrix_sync(bf, Bh + kt * 16 * TP + w * 16, TP);
            wmma::fragment<wmma::matrix_a, 16, 16, 16, half, wmma::row_major> af[4];
#pragma unroll
            for (int mt = 0; mt < 4; mt++)
                wmma::load_matrix_sync(af[mt], Ah + mt * 16 * TP + kt * 16, TP);
#pragma unroll
            for (int mt = 0; mt < 4; mt++) wmma::mma_sync(acc[mt], af[mt], bf, acc[mt]);
        }
    }
#pragma unroll
    for (int mt = 0; mt < 4; mt++)
        wmma::store_matrix_sync(out + (size_t)(mt * 16) * ldo + n0 + w * 16,
                                acc[mt], ldo, wmma::mem_row_major);
}

// ---------------- K4: LSTM gates + h_new fp16 image ----------------
__global__ void gates(const float* __restrict__ c, const float* __restrict__ bl,
                      float* __restrict__ o_h, float* __restrict__ o_c) {
    int b = blockIdx.y;
    int u = blockIdx.x * 256 + threadIdx.x;
    float zi = bl[u], zf = bl[u + UN], zg = bl[u + 2 * UN], zo = bl[u + 3 * UN];
#pragma unroll
    for (int s = 0; s < ZSPLITS; s++) {
        const float* zp = g_zpart + (size_t)s * BB * NZ + (size_t)b * NZ;
        zi += zp[u]; zf += zp[u + UN]; zg += zp[u + 2 * UN]; zo += zp[u + 3 * UN];
    }
    float cn = sigf(zf) * c[b * UN + u] + sigf(zi) * tanhfast(zg);
    float hn = sigf(zo) * tanhfast(cn);
    o_c[b * UN + u] = cn;
    o_h[b * UN + u] = hn;
    g_xv_h16[(size_t)b * UN + u] = __float2half_rn(hn);
}

// ---------------- softmax phase 1: per-slice max + sumexp ----------------
// grid (8 slices, 64 b), block 256; slice = 1000 float4 = 4000 logits
__global__ void softmax_p1(const float* __restrict__ bv) {
    int b = blockIdx.y, sl = blockIdx.x, tid = threadIdx.x;
    __shared__ float red[256];
    const float4* lg4 = (const float4*)(g_logits + (size_t)b * VOC) + sl * 1000;
    const float4* bv4 = (const float4*)bv + sl * 1000;
    float mx = -1e30f;
    for (int n = tid; n < 1000; n += 256) {
        float4 l = lg4[n], v = bv4[n];
        mx = fmaxf(mx, fmaxf(fmaxf(l.x + v.x, l.y + v.y), fmaxf(l.z + v.z, l.w + v.w)));
    }
    red[tid] = mx; __syncthreads();
    for (int s = 128; s > 0; s >>= 1) {
        if (tid < s) red[tid] = fmaxf(red[tid], red[tid + s]);
        __syncthreads();
    }
    float M = red[0]; __syncthreads();
    float sum = 0.f;
    for (int n = tid; n < 1000; n += 256) {
        float4 l = lg4[n], v = bv4[n];
        sum += __expf(l.x + v.x - M) + __expf(l.y + v.y - M)
             + __expf(l.z + v.z - M) + __expf(l.w + v.w - M);
    }
    red[tid] = sum; __syncthreads();
    for (int s = 128; s > 0; s >>= 1) {
        if (tid < s) red[tid] += red[tid + s];
        __syncthreads();
    }
    if (tid == 0) { g_smax[b * 8 + sl] = M; g_ssum[b * 8 + sl] = red[0]; }
}

// ---------------- softmax phase 2: merge + normalize ----------------
__global__ void softmax_p2(const float* __restrict__ bv, float* __restrict__ o_y) {
    int b = blockIdx.y, sl = blockIdx.x, tid = threadIdx.x;
    float M = -1e30f;
#pragma unroll
    for (int i = 0; i < 8; i++) M = fmaxf(M, g_smax[b * 8 + i]);
    float S = 0.f;
#pragma unroll
    for (int i = 0; i < 8; i++) S += g_ssum[b * 8 + i] * __expf(g_smax[b * 8 + i] - M);
    float inv = 1.0f / S;
    const float4* lg4 = (const float4*)(g_logits + (size_t)b * VOC) + sl * 1000;
    const float4* bv4 = (const float4*)bv + sl * 1000;
    float4* oy4 = (float4*)(o_y + (size_t)b * VOC) + sl * 1000;
    for (int n = tid; n < 1000; n += 256) {
        float4 l = lg4[n], v = bv4[n];
        oy4[n] = make_float4(__expf(l.x + v.x - M) * inv, __expf(l.y + v.y - M) * inv,
                             __expf(l.z + v.z - M) * inv, __expf(l.w + v.w - M) * inv);
    }
}

// ---------------- launch ----------------
extern "C" void kernel_launch(void* const* d_in, const int* in_sizes, int n_in,
                              void* d_out, int out_size) {
    (void)in_sizes; (void)n_in; (void)out_size;
    const int*   X   = (const int*)d_in[0];
    const float* a   = (const float*)d_in[1];
    const float* h   = (const float*)d_in[2];
    const float* c   = (const float*)d_in[3];
    const float* emb = (const float*)d_in[4];
    // d_in[5..10] dead (softmax over size-1 axis == 1)
    const float* Wx  = (const float*)d_in[11];
    const float* Wh  = (const float*)d_in[12];
    const float* bl  = (const float*)d_in[13];
    const float* Wv  = (const float*)d_in[14];
    const float* bv  = (const float*)d_in[15];

    float* out     = (float*)d_out;
    float* o_y     = out;
    float* o_ctx   = o_y + (size_t)BB * VOC;
    float* o_alpha = o_ctx + BB * AD;
    float* o_h     = o_alpha + BB * TXX;
    float* o_c     = o_h + BB * UN;

    ctx_partial<<<dim3(TCH, 64), 256>>>(a);
    ctx_finalize<<<dim3(4, 64), 256>>>(X, emb, h, o_ctx, o_alpha);
    // z part A: ctx rows (K=1024, Wx rows 0..1023), bf16 3-term; 4 splits x 4 chunks
    wgemm<<<dim3(NZ / 64, 4), 128>>>(Wx, NZ, AD, 4, NZ);
    // z part B: emb+h rows (K=1536: Wx rows 1024..1535 then Wh), fp16; 4 splits x 6 chunks
    hgemm16<<<dim3(NZ / 64, 4), 128>>>(Wx + (size_t)AD * NZ, Wh, ED, NZ,
                                       /*in_sel=*/0, ED + UN, 6, /*out_sel=*/0, 4, NZ);
    gates<<<dim3(4, 64), 256>>>(c, bl, o_h, o_c);
    // logits = h_new@Wv : fp16 single-pass, 500 n-blocks
    hgemm16<<<dim3(VOC / 64, 1), 128>>>(Wv, Wv, 0x40000000, VOC,
                                        /*in_sel=*/1, UN, UN / 64, /*out_sel=*/1, 0, VOC);
    softmax_p1<<<dim3(8, 64), 256>>>(bv);
    softmax_p2<<<dim3(8, 64), 256>>>(bv, o_y);
}

// round 12
// speedup vs baseline: 1.0622x; 1.0622x over previous
#include <cuda_runtime.h>
#include <cuda_bf16.h>
#include <cuda_fp16.h>
#include <mma.h>

using namespace nvcuda;

#define BB    64
#define TXX   1024
#define AD    1024
#define UN    1024
#define VOC   32000
#define ED    512
#define KXIN  2560
#define NZ    4096
#define ZSPLITS 16     // 8 (bf16 ctx) + 8 (fp16 emb+h)
#define TCH   16

#define TP 72          // smem tile pitch (elems): 64 + 8

// ---------------- scratch (__device__ globals; NEVER passed from host) ----------------
__device__ __align__(16) float g_pctx[TCH * BB * AD];
__device__ __align__(16) __nv_bfloat16 g_xz_hi[BB * AD];     // ctx rows (K 0..1023)
__device__ __align__(16) __nv_bfloat16 g_xz_lo[BB * AD];
__device__ __align__(16) half g_xe_h16[BB * (ED + UN)];      // emb+h rows (K 1024..2559)
__device__ __align__(16) half g_xv_h16[BB * UN];
__device__ __align__(16) float g_zpart[ZSPLITS * BB * NZ];
__device__ __align__(16) float g_logits[BB * VOC];
__device__ float g_smax[BB * 8];
__device__ float g_ssum[BB * 8];

__device__ __forceinline__ float sigf(float x) { return 1.0f / (1.0f + __expf(-x)); }
__device__ __forceinline__ float tanhfast(float x) {
    float e = __expf(2.0f * x);
    return 1.0f - 2.0f / (e + 1.0f);
}

__device__ __forceinline__ void split_write(__nv_bfloat16* hi, __nv_bfloat16* lo,
                                            size_t idx, float v) {
    __nv_bfloat16 h = __float2bfloat16(v);
    hi[idx] = h;
    lo[idx] = __float2bfloat16(v - __bfloat162float(h));
}

// ---------------- K1: context partial sums ----------------
__global__ void ctx_partial(const float* __restrict__ a) {
    int d4 = threadIdx.x;
    int b  = blockIdx.y;
    int t0 = blockIdx.x * 64;
    const float4* p = (const float4*)(a + ((size_t)b * TXX + t0) * AD) + d4;
    float4 s = make_float4(0.f, 0.f, 0.f, 0.f);
#pragma unroll 8
    for (int t = 0; t < 64; t++) {
        float4 v = p[(size_t)t * 256];
        s.x += v.x; s.y += v.y; s.z += v.z; s.w += v.w;
    }
    ((float4*)g_pctx)[((size_t)blockIdx.x * BB + b) * 256 + d4] = s;
}

// ---------------- K2: finalize ctx + build operand images ----------------
__global__ void ctx_finalize(const int* __restrict__ X, const float* __restrict__ emb,
                             const float* __restrict__ h,
                             float* __restrict__ o_ctx, float* __restrict__ o_alpha) {
    int b = blockIdx.y;
    int d = blockIdx.x * 256 + threadIdx.x;
    float s = 0.f;
#pragma unroll
    for (int j = 0; j < TCH; j++) s += g_pctx[((size_t)j * BB + b) * AD + d];
    o_ctx[b * AD + d]    = s;
    o_alpha[b * TXX + d] = 1.0f;
    split_write(g_xz_hi, g_xz_lo, (size_t)b * AD + d, s);
    if (d < ED) {
        int tok = X[b];
        g_xe_h16[(size_t)b * (ED + UN) + d] = __float2half_rn(emb[(size_t)tok * ED + d]);
    }
    g_xe_h16[(size_t)b * (ED + UN) + ED + d] = __float2half_rn(h[b * UN + d]);
}

// ---------------- fused z-GEMM: one wide launch, two block-level paths ----------------
// grid (64 n-blocks, 16 ky). ky<8: bf16 3-term on ctx rows (K=1024, 2 chunks).
// ky>=8: fp16 single-pass on emb+h rows (K=1536, 3 chunks).
__global__ void __launch_bounds__(128, 4)
zgemm_fused(const float* __restrict__ Wx, const float* __restrict__ Wh) {
    __shared__ __align__(32) char smbuf[36864];
    int tid = threadIdx.x, w = tid >> 5;
    int n0 = blockIdx.x * 64;
    int ky = blockIdx.y;
    float* out = g_zpart + (size_t)ky * BB * NZ;

    wmma::fragment<wmma::accumulator, 16, 16, 16, float> acc[4];
#pragma unroll
    for (int i = 0; i < 4; i++) wmma::fill_fragment(acc[i], 0.0f);

    if (ky < 8) {
        // ===== bf16 hi/lo 3-term, ctx segment: K chunks [ky*128, ky*128+128) =====
        __nv_bfloat16* Ah = (__nv_bfloat16*)smbuf;
        __nv_bfloat16* Al = Ah + 4608;
        __nv_bfloat16* Bh = Ah + 9216;
        __nv_bfloat16* Bl = Ah + 13824;
        int k0 = ky * 128;

        float4 pf[8];
        auto ldB = [&](int kg0) {
#pragma unroll
            for (int i = 0; i < 8; i++) {
                int idx = tid + i * 128;
                int k = idx >> 4, f4c = idx & 15;
                pf[i] = __ldg((const float4*)(Wx + (size_t)(kg0 + k) * NZ + n0) + f4c);
            }
        };
        ldB(k0);
#pragma unroll
        for (int ci = 0; ci < 2; ci++) {
            int kg0 = k0 + ci * 64;
            __syncthreads();
#pragma unroll
            for (int i = 0; i < 4; i++) {
                int idx = tid + i * 128;
                int row = idx >> 3, j = idx & 7;
                size_t so = ((size_t)row * AD + kg0) / 8 + j;
                ((uint4*)Ah)[row * 9 + j] = ((const uint4*)g_xz_hi)[so];
                ((uint4*)Al)[row * 9 + j] = ((const uint4*)g_xz_lo)[so];
            }
#pragma unroll
            for (int i = 0; i < 8; i++) {
                int idx = tid + i * 128;
                int k = idx >> 4, f4c = idx & 15;
                float4 v = pf[i];
                __nv_bfloat16 h0 = __float2bfloat16(v.x), h1 = __float2bfloat16(v.y);
                __nv_bfloat16 h2 = __float2bfloat16(v.z), h3 = __float2bfloat16(v.w);
                __nv_bfloat16 l0 = __float2bfloat16(v.x - __bfloat162float(h0));
                __nv_bfloat16 l1 = __float2bfloat16(v.y - __bfloat162float(h1));
                __nv_bfloat16 l2 = __float2bfloat16(v.z - __bfloat162float(h2));
                __nv_bfloat16 l3 = __float2bfloat16(v.w - __bfloat162float(h3));
                int bo = k * TP + f4c * 4;
                *(__nv_bfloat162*)(Bh + bo)     = __halves2bfloat162(h0, h1);
                *(__nv_bfloat162*)(Bh + bo + 2) = __halves2bfloat162(h2, h3);
                *(__nv_bfloat162*)(Bl + bo)     = __halves2bfloat162(l0, l1);
                *(__nv_bfloat162*)(Bl + bo + 2) = __halves2bfloat162(l2, l3);
            }
            __syncthreads();
            if (ci == 0) ldB(kg0 + 64);
#pragma unroll
            for (int kt = 0; kt < 4; kt++) {
                wmma::fragment<wmma::matrix_b, 16, 16, 16, __nv_bfloat16, wmma::row_major> bh, bl;
                wmma::load_matrix_sync(bh, Bh + kt * 16 * TP + w * 16, TP);
                wmma::load_matrix_sync(bl, Bl + kt * 16 * TP + w * 16, TP);
                wmma::fragment<wmma::matrix_a, 16, 16, 16, __nv_bfloat16, wmma::row_major> af[4];
#pragma unroll
                for (int mt = 0; mt < 4; mt++)
                    wmma::load_matrix_sync(af[mt], Ah + mt * 16 * TP + kt * 16, TP);
#pragma unroll
                for (int mt = 0; mt < 4; mt++) wmma::mma_sync(acc[mt], af[mt], bh, acc[mt]);
#pragma unroll
                for (int mt = 0; mt < 4; mt++) wmma::mma_sync(acc[mt], af[mt], bl, acc[mt]);
#pragma unroll
                for (int mt = 0; mt < 4; mt++)
                    wmma::load_matrix_sync(af[mt], Al + mt * 16 * TP + kt * 16, TP);
#pragma unroll
                for (int mt = 0; mt < 4; mt++) wmma::mma_sync(acc[mt], af[mt], bh, acc[mt]);
            }
        }
    } else {
        // ===== fp16 single-pass, emb+h segment: K chunks [kyb*192, kyb*192+192) =====
        half* Ah = (half*)smbuf;
        half* Bh = Ah + 4608;
        const float* Wa = Wx + (size_t)AD * NZ;   // Wx rows 1024..1535
        int k0 = (ky - 8) * 192;

        uint4  pa[4];
        float4 pb[8];
        auto ldAB = [&](int kg0) {
#pragma unroll
            for (int i = 0; i < 4; i++) {
                int idx = tid + i * 128;
                int row = idx >> 3, j = idx & 7;
                pa[i] = ((const uint4*)g_xe_h16)[(size_t)row * ((ED + UN) / 8) + kg0 / 8 + j];
            }
#pragma unroll
            for (int i = 0; i < 8; i++) {
                int idx = tid + i * 128;
                int k = idx >> 4, f4c = idx & 15;
                int kg = kg0 + k;
                const float* wrow = (kg < ED) ? (Wa + (size_t)kg * NZ)
                                              : (Wh + (size_t)(kg - ED) * NZ);
                pb[i] = __ldg((const float4*)(wrow + n0) + f4c);
            }
        };
        ldAB(k0);
#pragma unroll
        for (int ci = 0; ci < 3; ci++) {
            __syncthreads();
#pragma unroll
            for (int i = 0; i < 4; i++) {
                int idx = tid + i * 128;
                int row = idx >> 3, j = idx & 7;
                ((uint4*)Ah)[row * 9 + j] = pa[i];
            }
#pragma unroll
            for (int i = 0; i < 8; i++) {
                int idx = tid + i * 128;
                int k = idx >> 4, f4c = idx & 15;
                float4 v = pb[i];
                half2 h01 = __floats2half2_rn(v.x, v.y);
                half2 h23 = __floats2half2_rn(v.z, v.w);
                int bo = k * TP + f4c * 4;
                *(half2*)(Bh + bo)     = h01;
                *(half2*)(Bh + bo + 2) = h23;
            }
            __syncthreads();
            if (ci + 1 < 3) ldAB(k0 + (ci + 1) * 64);
#pragma unroll
            for (int kt = 0; kt < 4; kt++) {
                wmma::fragment<wmma::matrix_b, 16, 16, 16, half, wmma::row_major> bf;
                wmma::load_matrix_sync(bf, Bh + kt * 16 * TP + w * 16, TP);
                wmma::fragment<wmma::matrix_a, 16, 16, 16, half, wmma::row_major> af[4];
#pragma unroll
                for (int mt = 0; mt < 4; mt++)
                    wmma::load_matrix_sync(af[mt], Ah + mt * 16 * TP + kt * 16, TP);
#pragma unroll
                for (int mt = 0; mt < 4; mt++) wmma::mma_sync(acc[mt], af[mt], bf, acc[mt]);
            }
        }
    }
#pragma unroll
    for (int mt = 0; mt < 4; mt++)
        wmma::store_matrix_sync(out + (size_t)(mt * 16) * NZ + n0 + w * 16,
                                acc[mt], NZ, wmma::mem_row_major);
}

// ---------------- vgemm16: logits = h_new @ Wv  (fp16 single-pass) ----------------
__global__ void __launch_bounds__(128, 4)
vgemm16(const float* __restrict__ Wv) {
    __shared__ __align__(32) half sm[2 * 64 * TP];
    half* Ah = sm;
    half* Bh = sm + 4608;

    int tid = threadIdx.x, w = tid >> 5;
    int n0 = blockIdx.x * 64;

    wmma::fragment<wmma::accumulator, 16, 16, 16, float> acc[4];
#pragma unroll
    for (int i = 0; i < 4; i++) wmma::fill_fragment(acc[i], 0.0f);

    uint4  pa[4];
    float4 pb[8];
    auto ldAB = [&](int kg0) {
#pragma unroll
        for (int i = 0; i < 4; i++) {
            int idx = tid + i * 128;
            int row = idx >> 3, j = idx & 7;
            pa[i] = ((const uint4*)g_xv_h16)[(size_t)row * (UN / 8) + kg0 / 8 + j];
        }
#pragma unroll
        for (int i = 0; i < 8; i++) {
            int idx = tid + i * 128;
            int k = idx >> 4, f4c = idx & 15;
            pb[i] = __ldg((const float4*)(Wv + (size_t)(kg0 + k) * VOC + n0) + f4c);
        }
    };

    ldAB(0);
    for (int ci = 0; ci < UN / 64; ci++) {
        __syncthreads();
#pragma unroll
        for (int i = 0; i < 4; i++) {
            int idx = tid + i * 128;
            int row = idx >> 3, j = idx & 7;
            ((uint4*)Ah)[row * 9 + j] = pa[i];
        }
#pragma unroll
        for (int i = 0; i < 8; i++) {
            int idx = tid + i * 128;
            int k = idx >> 4, f4c = idx & 15;
            float4 v = pb[i];
            half2 h01 = __floats2half2_rn(v.x, v.y);
            half2 h23 = __floats2half2_rn(v.z, v.w);
            int bo = k * TP + f4c * 4;
            *(half2*)(Bh + bo)     = h01;
            *(half2*)(Bh + bo + 2) = h23;
        }
        __syncthreads();
        if (ci + 1 < UN / 64) ldAB((ci + 1) * 64);
#pragma unroll
        for (int kt = 0; kt < 4; kt++) {
            wmma::fragment<wmma::matrix_b, 16, 16, 16, half, wmma::row_major> bf;
            wmma::load_matrix_sync(bf, Bh + kt * 16 * TP + w * 16, TP);
            wmma::fragment<wmma::matrix_a, 16, 16, 16, half, wmma::row_major> af[4];
#pragma unroll
            for (int mt = 0; mt < 4; mt++)
                wmma::load_matrix_sync(af[mt], Ah + mt * 16 * TP + kt * 16, TP);
#pragma unroll
            for (int mt = 0; mt < 4; mt++) wmma::mma_sync(acc[mt], af[mt], bf, acc[mt]);
        }
    }
#pragma unroll
    for (int mt = 0; mt < 4; mt++)
        wmma::store_matrix_sync(g_logits + (size_t)(mt * 16) * VOC + n0 + w * 16,
                                acc[mt], VOC, wmma::mem_row_major);
}

// ---------------- K4: LSTM gates + h_new fp16 image ----------------
__global__ void gates(const float* __restrict__ c, const float* __restrict__ bl,
                      float* __restrict__ o_h, float* __restrict__ o_c) {
    int b = blockIdx.y;
    int u = blockIdx.x * 256 + threadIdx.x;
    float zi = bl[u], zf = bl[u + UN], zg = bl[u + 2 * UN], zo = bl[u + 3 * UN];
#pragma unroll
    for (int s = 0; s < ZSPLITS; s++) {
        const float* zp = g_zpart + (size_t)s * BB * NZ + (size_t)b * NZ;
        zi += zp[u]; zf += zp[u + UN]; zg += zp[u + 2 * UN]; zo += zp[u + 3 * UN];
    }
    float cn = sigf(zf) * c[b * UN + u] + sigf(zi) * tanhfast(zg);
    float hn = sigf(zo) * tanhfast(cn);
    o_c[b * UN + u] = cn;
    o_h[b * UN + u] = hn;
    g_xv_h16[(size_t)b * UN + u] = __float2half_rn(hn);
}

// ---------------- softmax phase 1: per-slice max + sumexp ----------------
__global__ void softmax_p1(const float* __restrict__ bv) {
    int b = blockIdx.y, sl = blockIdx.x, tid = threadIdx.x;
    __shared__ float red[256];
    const float4* lg4 = (const float4*)(g_logits + (size_t)b * VOC) + sl * 1000;
    const float4* bv4 = (const float4*)bv + sl * 1000;
    float mx = -1e30f;
    for (int n = tid; n < 1000; n += 256) {
        float4 l = lg4[n], v = bv4[n];
        mx = fmaxf(mx, fmaxf(fmaxf(l.x + v.x, l.y + v.y), fmaxf(l.z + v.z, l.w + v.w)));
    }
    red[tid] = mx; __syncthreads();
    for (int s = 128; s > 0; s >>= 1) {
        if (tid < s) red[tid] = fmaxf(red[tid], red[tid + s]);
        __syncthreads();
    }
    float M = red[0]; __syncthreads();
    float sum = 0.f;
    for (int n = tid; n < 1000; n += 256) {
        float4 l = lg4[n], v = bv4[n];
        sum += __expf(l.x + v.x - M) + __expf(l.y + v.y - M)
             + __expf(l.z + v.z - M) + __expf(l.w + v.w - M);
    }
    red[tid] = sum; __syncthreads();
    for (int s = 128; s > 0; s >>= 1) {
        if (tid < s) red[tid] += red[tid + s];
        __syncthreads();
    }
    if (tid == 0) { g_smax[b * 8 + sl] = M; g_ssum[b * 8 + sl] = red[0]; }
}

// ---------------- softmax phase 2: merge + normalize ----------------
__global__ void softmax_p2(const float* __restrict__ bv, float* __restrict__ o_y) {
    int b = blockIdx.y, sl = blockIdx.x, tid = threadIdx.x;
    float M = -1e30f;
#pragma unroll
    for (int i = 0; i < 8; i++) M = fmaxf(M, g_smax[b * 8 + i]);
    float S = 0.f;
#pragma unroll
    for (int i = 0; i < 8; i++) S += g_ssum[b * 8 + i] * __expf(g_smax[b * 8 + i] - M);
    float inv = 1.0f / S;
    const float4* lg4 = (const float4*)(g_logits + (size_t)b * VOC) + sl * 1000;
    const float4* bv4 = (const float4*)bv + sl * 1000;
    float4* oy4 = (float4*)(o_y + (size_t)b * VOC) + sl * 1000;
    for (int n = tid; n < 1000; n += 256) {
        float4 l = lg4[n], v = bv4[n];
        oy4[n] = make_float4(__expf(l.x + v.x - M) * inv, __expf(l.y + v.y - M) * inv,
                             __expf(l.z + v.z - M) * inv, __expf(l.w + v.w - M) * inv);
    }
}

// ---------------- launch ----------------
extern "C" void kernel_launch(void* const* d_in, const int* in_sizes, int n_in,
                              void* d_out, int out_size) {
    (void)in_sizes; (void)n_in; (void)out_size;
    const int*   X   = (const int*)d_in[0];
    const float* a   = (const float*)d_in[1];
    const float* h   = (const float*)d_in[2];
    const float* c   = (const float*)d_in[3];
    const float* emb = (const float*)d_in[4];
    // d_in[5..10] dead (softmax over size-1 axis == 1)
    const float* Wx  = (const float*)d_in[11];
    const float* Wh  = (const float*)d_in[12];
    const float* bl  = (const float*)d_in[13];
    const float* Wv  = (const float*)d_in[14];
    const float* bv  = (const float*)d_in[15];

    float* out     = (float*)d_out;
    float* o_y     = out;
    float* o_ctx   = o_y + (size_t)BB * VOC;
    float* o_alpha = o_ctx + BB * AD;
    float* o_h     = o_alpha + BB * TXX;
    float* o_c     = o_h + BB * UN;

    ctx_partial<<<dim3(TCH, 64), 256>>>(a);
    ctx_finalize<<<dim3(4, 64), 256>>>(X, emb, h, o_ctx, o_alpha);
    // fused z: 64 n-blocks x 16 ky = 1024 blocks (8 bf16-ctx + 8 fp16-emb/h splits)
    zgemm_fused<<<dim3(NZ / 64, 16), 128>>>(Wx, Wh);
    gates<<<dim3(4, 64), 256>>>(c, bl, o_h, o_c);
    vgemm16<<<dim3(VOC / 64, 1), 128>>>(Wv);
    softmax_p1<<<dim3(8, 64), 256>>>(bv);
    softmax_p2<<<dim3(8, 64), 256>>>(bv, o_y);
}